// round 15
// baseline (speedup 1.0000x reference)
#include <cuda_runtime.h>

#define B_  128
#define T_  64
#define N_  81
#define M_  128
#define G4_ 512

typedef unsigned long long ull;

__device__ __forceinline__ float frcp(float x) {
    float r; asm("rcp.approx.ftz.f32 %0, %1;" : "=f"(r) : "f"(x)); return r;
}
__device__ __forceinline__ float sigm(float x) {
    return frcp(1.0f + __expf(-x));
}
__device__ __forceinline__ float tanhe(float x) {           // exp-based, accurate
    return 2.0f * frcp(1.0f + __expf(-2.0f * x)) - 1.0f;
}
__device__ __forceinline__ float tanhap(float x) {          // HW tanh, 1 MUFU
    float r; asm("tanh.approx.f32 %0, %1;" : "=f"(r) : "f"(x)); return r;
}
__device__ __forceinline__ ull pk2(float a, float b) {
    ull r; asm("mov.b64 %0, {%1, %2};" : "=l"(r) : "f"(a), "f"(b)); return r;
}
__device__ __forceinline__ ull fma2(ull a, ull b, ull c) {
    ull d;
    asm("fma.rn.f32x2 %0, %1, %2, %3;" : "=l"(d) : "l"(a), "l"(b), "l"(c));
    return d;
}
__device__ __forceinline__ void unpk2(ull v, float& lo, float& hi) {
    asm("mov.b64 {%0, %1}, %2;" : "=f"(lo), "=f"(hi) : "l"(v));
}

// ---------------------------------------------------------------------------
// One block per b, 512 threads, 1 block/SM. R10 structure; phase 3 split into
// 3a (softmax + global LUT table) and 3b (register-X streaming).
// smem (floats):
//  HC  @0     : hc[64][257] = 16448      -> Us[96][65] = 6240 (phase U+)
//  XST @16448 : Xst[81][66] = 5346 (gates) -> As[64][65] = 4160 (phase A+)
//  XS  @21796 : Xs[5184] row-major (loaded in phase U, lives to end)
//  C   @26980 : gates Ws[81*256] = 20736
//               -> phase A: Wes chunk 4096 | phase U: Ues 4096
//               -> phase 3: LUT[64][81] float4 = 20736 (exact fit)
//  AL  @47716 : alpha rows [64][81] = 5184
//  Z   @52900 : z[512]; VS @53412; UB @53476; HS @53540
//  TOT 53668 floats = 214672 B
// ---------------------------------------------------------------------------
#define HC_OFF    0
#define HC_PITCH  257
#define US_OFF    0
#define US_PITCH  65
#define XST_OFF   16448
#define XST_PITCH 66
#define AS_OFF    16448
#define AS_PITCH  65
#define XS_OFF    21796
#define C_OFF     26980
#define WS_OFF    C_OFF
#define WES_OFF   C_OFF
#define UES_OFF   C_OFF
#define LUT_OFF   C_OFF
#define AL_OFF    47716
#define Z_OFF     52900
#define VS_OFF    53412
#define UB_OFF    53476
#define HS_OFF    53540
#define TOT_SMEM  (53668 * 4)

__global__ void __launch_bounds__(512, 1)
k_all(const float* __restrict__ X,   const float* __restrict__ h0,
      const float* __restrict__ s0,  const float* __restrict__ Wl,
      const float* __restrict__ Ul,  const float* __restrict__ bl,
      const float* __restrict__ Wew, const float* __restrict__ Web,
      const float* __restrict__ Uew, const float* __restrict__ Ueb,
      const float* __restrict__ vew, float* __restrict__ out) {
    extern __shared__ float sm[];
    float* hcsm = sm + HC_OFF;
    float* Xst  = sm + XST_OFF;
    float* Xs   = sm + XS_OFF;
    float* Ws   = sm + WS_OFF;
    float* zsm  = sm + Z_OFF;
    float* vs   = sm + VS_OFF;
    float* ub   = sm + UB_OFF;
    float* hs   = sm + HS_OFF;
    int b = blockIdx.x, tid = threadIdx.x;
    int wid = tid >> 5, lane = tid & 31;

    // ---- prologue: Xst (transposed X), h0, vs, ub ----
    for (int idx = tid; idx < T_ * N_; idx += 512) {
        int t = idx / N_, k = idx - t * N_;
        Xst[k * XST_PITCH + t] = X[b * T_ * N_ + idx];
    }
    if (tid < M_) hs[tid] = h0[b * M_ + tid];
    else if (tid < M_ + 64)       vs[tid - M_]       = vew[tid - M_];
    else if (tid < M_ + 128)      ub[tid - M_ - 64]  = Ueb[tid - M_ - 64];
    __syncthreads();

    // ---- z = h0 @ U_lstm + b_lstm (one g per thread, MLP-16) ----
    {
        const float* Up = Ul + tid;
        float a0 = bl[tid], a1 = 0.f, a2 = 0.f, a3 = 0.f;
#pragma unroll
        for (int k = 0; k < M_; k += 16) {
            float u0  = Up[(k + 0)  * G4_], u1  = Up[(k + 1)  * G4_];
            float u2  = Up[(k + 2)  * G4_], u3  = Up[(k + 3)  * G4_];
            float u4  = Up[(k + 4)  * G4_], u5  = Up[(k + 5)  * G4_];
            float u6  = Up[(k + 6)  * G4_], u7  = Up[(k + 7)  * G4_];
            float u8  = Up[(k + 8)  * G4_], u9  = Up[(k + 9)  * G4_];
            float u10 = Up[(k + 10) * G4_], u11 = Up[(k + 11) * G4_];
            float u12 = Up[(k + 12) * G4_], u13 = Up[(k + 13) * G4_];
            float u14 = Up[(k + 14) * G4_], u15 = Up[(k + 15) * G4_];
            a0 += hs[k + 0]  * u0;  a1 += hs[k + 1]  * u1;
            a2 += hs[k + 2]  * u2;  a3 += hs[k + 3]  * u3;
            a0 += hs[k + 4]  * u4;  a1 += hs[k + 5]  * u5;
            a2 += hs[k + 6]  * u6;  a3 += hs[k + 7]  * u7;
            a0 += hs[k + 8]  * u8;  a1 += hs[k + 9]  * u9;
            a2 += hs[k + 10] * u10; a3 += hs[k + 11] * u11;
            a0 += hs[k + 12] * u12; a1 += hs[k + 13] * u13;
            a2 += hs[k + 14] * u14; a3 += hs[k + 15] * u15;
        }
        zsm[tid] = (a0 + a1) + (a2 + a3);
    }

    // ---- gates: X@W_lstm + z ; LSTM cell ; hc -> smem (R10 structure) ----
    {
        int tg = wid & 7, ml = wid >> 3;
        for (int stage = 0; stage < 2; stage++) {
            __syncthreads();
            for (int idx = tid; idx < 81 * 256; idx += 512) {
                int k = idx >> 8, j = idx & 255;
                int g = j >> 6, c = j & 63;
                Ws[k * 256 + c * 4 + g] = Wl[k * G4_ + g * M_ + stage * 64 + c];
            }
            __syncthreads();
            int m = stage * 64 + ml * 32 + lane;
            float zi = zsm[0 * M_ + m];
            float zf = zsm[1 * M_ + m];
            float zg = zsm[2 * M_ + m];
            float zo = zsm[3 * M_ + m];
            float sv = s0[b * M_ + m];

            for (int th = 0; th < 2; th++) {
                int trow = th * 32 + tg * 4;
                ull acc[4][2];
#pragma unroll
                for (int g = 0; g < 4; g++)
#pragma unroll
                    for (int p = 0; p < 2; p++) acc[g][p] = 0ull;

#pragma unroll 3
                for (int k = 0; k < 81; k++) {
                    const float* xr = &Xst[k * XST_PITCH + trow];
                    ull x0 = *(const ull*)(xr + 0);
                    ull x1 = *(const ull*)(xr + 2);
                    float4 w4 = *(const float4*)&Ws[k * 256 + (ml * 32 + lane) * 4];
                    ull di = pk2(w4.x, w4.x);
                    ull df = pk2(w4.y, w4.y);
                    ull dg = pk2(w4.z, w4.z);
                    ull do_ = pk2(w4.w, w4.w);
                    acc[0][0] = fma2(x0, di, acc[0][0]);
                    acc[0][1] = fma2(x1, di, acc[0][1]);
                    acc[1][0] = fma2(x0, df, acc[1][0]);
                    acc[1][1] = fma2(x1, df, acc[1][1]);
                    acc[2][0] = fma2(x0, dg, acc[2][0]);
                    acc[2][1] = fma2(x1, dg, acc[2][1]);
                    acc[3][0] = fma2(x0, do_, acc[3][0]);
                    acc[3][1] = fma2(x1, do_, acc[3][1]);
                }
#pragma unroll
                for (int p = 0; p < 2; p++) {
                    float vi[2], vf[2], vg[2], vo[2];
                    unpk2(acc[0][p], vi[0], vi[1]);
                    unpk2(acc[1][p], vf[0], vf[1]);
                    unpk2(acc[2][p], vg[0], vg[1]);
                    unpk2(acc[3][p], vo[0], vo[1]);
#pragma unroll
                    for (int hh_ = 0; hh_ < 2; hh_++) {
                        int tl = trow + 2 * p + hh_;
                        float iv = sigm(vi[hh_] + zi);
                        float fv = sigm(vf[hh_] + zf);
                        float gv = tanhe(vg[hh_] + zg);
                        float ov = sigm(vo[hh_] + zo);
                        float cc = fv * sv + iv * gv;
                        float hv = ov * tanhe(cc);
                        hcsm[tl * HC_PITCH + m]      = hv;
                        hcsm[tl * HC_PITCH + M_ + m] = cc;
                    }
                }
            }
        }
    }

    // ---- phase A: chunked Wes (R10 form); As -> dead Xst region ----
    float* As = sm + AS_OFF;
    {
        float* Wes = sm + WES_OFF;
        int r0 = (tid >> 4) * 2;
        int c0 = (tid & 15) * 4;
        float acc[2][4];
#pragma unroll
        for (int i = 0; i < 2; i++)
#pragma unroll
            for (int j = 0; j < 4; j++) acc[i][j] = Web[c0 + j];

        for (int kc = 0; kc < 4; kc++) {
            __syncthreads();                     // gates Ws / prev Wes dead
            for (int idx = tid; idx < 4096; idx += 512)
                Wes[idx] = Wew[kc * 4096 + idx];
            __syncthreads();
#pragma unroll 4
            for (int k = 0; k < 64; k++) {
                float a0 = hcsm[r0 * HC_PITCH + kc * 64 + k];
                float a1 = hcsm[(r0 + 1) * HC_PITCH + kc * 64 + k];
                float4 w = *(const float4*)&Wes[k * 64 + c0];
                acc[0][0] += a0 * w.x; acc[0][1] += a0 * w.y;
                acc[0][2] += a0 * w.z; acc[0][3] += a0 * w.w;
                acc[1][0] += a1 * w.x; acc[1][1] += a1 * w.y;
                acc[1][2] += a1 * w.z; acc[1][3] += a1 * w.w;
            }
        }
        __syncthreads();                         // all Xst reads long dead; safe
#pragma unroll
        for (int i = 0; i < 2; i++)
#pragma unroll
            for (int j = 0; j < 4; j++)
                As[(r0 + i) * AS_PITCH + c0 + j] = acc[i][j];
    }

    // ---- phase U: U[i][k] = sum_t X[b,t,i]*Ue_w[t,k] + Ue_b[k] ----
    float* Us = sm + US_OFF;
    {
        float* Ues = sm + UES_OFF;
        __syncthreads();                         // hcsm + Wes reads done
        for (int idx = tid; idx < 5184; idx += 512) Xs[idx] = X[b * 5184 + idx];
        for (int idx = tid; idx < 4096; idx += 512) Ues[idx] = Uew[idx];
        __syncthreads();

        for (int w = tid; w < 648; w += 512) {   // 81 i x 8 k-octets
            int i  = w >> 3;
            int k0 = (w & 7) * 8;
            float4 a0 = *(const float4*)&ub[k0];
            float4 a1 = *(const float4*)&ub[k0 + 4];
#pragma unroll 4
            for (int t = 0; t < T_; t++) {
                float  x  = Xs[t * N_ + i];
                float4 u0 = *(const float4*)&Ues[t * 64 + k0];
                float4 u1 = *(const float4*)&Ues[t * 64 + k0 + 4];
                a0.x += x * u0.x; a0.y += x * u0.y; a0.z += x * u0.z; a0.w += x * u0.w;
                a1.x += x * u1.x; a1.y += x * u1.y; a1.z += x * u1.z; a1.w += x * u1.w;
            }
            float* up = &Us[i * US_PITCH + k0];
            up[0] = a0.x; up[1] = a0.y; up[2] = a0.z; up[3] = a0.w;
            up[4] = a1.x; up[5] = a1.y; up[6] = a1.z; up[7] = a1.w;
        }
        // zero-pad rows 81..95 so lane+64 reads stay in-region
        for (int idx = tid; idx < (96 - N_) * US_PITCH; idx += 512)
            Us[N_ * US_PITCH + idx] = 0.0f;
    }

    // ---- phase 3a: scores + softmax + LUT table for ALL t ----
    __syncthreads();                             // Ues dead -> LUT region free
    {
        bool v2 = (lane + 64 < N_);
        for (int t = wid; t < T_; t += 16) {
            float a0 = 0.f, a1 = 0.f, a2 = 0.f;
            const float* Ap = &As[t * AS_PITCH];
            const float* U0 = &Us[lane * US_PITCH];
            const float* U1 = &Us[(lane + 32) * US_PITCH];
            const float* U2 = &Us[(lane + 64) * US_PITCH];
#pragma unroll 4
            for (int k = 0; k < 64; k++) {
                float av = Ap[k], vv = vs[k];
                a0 += vv * tanhap(av + U0[k]);
                a1 += vv * tanhap(av + U1[k]);
                a2 += vv * tanhap(av + U2[k]);
            }
            if (!v2) a2 = -1e30f;
            float mx = fmaxf(fmaxf(a0, a1), a2);
#pragma unroll
            for (int off = 16; off; off >>= 1)
                mx = fmaxf(mx, __shfl_xor_sync(0xffffffffu, mx, off));
            float e0 = __expf(a0 - mx);
            float e1 = __expf(a1 - mx);
            float e2 = __expf(a2 - mx);
            float sum = e0 + e1 + e2;
#pragma unroll
            for (int off = 16; off; off >>= 1)
                sum += __shfl_xor_sync(0xffffffffu, sum, off);
            float inv = frcp(sum);
            float* alw = sm + AL_OFF + t * 81;
            alw[lane]      = e0 * inv;
            alw[lane + 32] = e1 * inv;
            if (v2) alw[lane + 64] = e2 * inv;
            __syncwarp();

            // expanded float4 alpha LUT (period-81 mapping, gcd(4,81)=1)
            float4* lut = (float4*)(sm + LUT_OFF) + t * 81;
#pragma unroll
            for (int rr = 0; rr < 3; rr++) {
                int r = lane + rr * 32;
                if (r < N_) {
                    int i0 = (4 * r) % N_;
                    int i1 = i0 + 1; if (i1 >= N_) i1 -= N_;
                    int i2 = i1 + 1; if (i2 >= N_) i2 -= N_;
                    int i3 = i2 + 1; if (i3 >= N_) i3 -= N_;
                    lut[r] = make_float4(alw[i0], alw[i1], alw[i2], alw[i3]);
                }
            }
        }
    }

    // ---- phase 3b: register-X streaming; warp w owns j in [81w, 81w+81) ----
    __syncthreads();
    {
        const float4* X4s  = (const float4*)Xs;
        const float4* LUT4 = (const float4*)(sm + LUT_OFF);
        int j0 = wid * 81 + lane;
        int j1 = j0 + 32;
        int j2 = j0 + 64;
        bool has2 = (lane + 64 < 81);
        float4 x0 = X4s[j0];
        float4 x1 = X4s[j1];
        float4 x2 = has2 ? X4s[j2] : make_float4(0, 0, 0, 0);
        int r0 = lane, r1 = lane + 32, r2 = lane + 64;

        float4* O = (float4*)out + (size_t)b * 1296;
#pragma unroll 4
        for (int t = 0; t < T_; t++) {
            const float4* lt = LUT4 + t * 81;
            float4 a0 = lt[r0];
            float4 o0 = make_float4(x0.x * a0.x, x0.y * a0.y,
                                    x0.z * a0.z, x0.w * a0.w);
            __stcs(&O[j0], o0);
            float4 a1 = lt[r1];
            float4 o1 = make_float4(x1.x * a1.x, x1.y * a1.y,
                                    x1.z * a1.z, x1.w * a1.w);
            __stcs(&O[j1], o1);
            if (has2) {
                float4 a2 = lt[r2];
                float4 o2 = make_float4(x2.x * a2.x, x2.y * a2.y,
                                        x2.z * a2.z, x2.w * a2.w);
                __stcs(&O[j2], o2);
            }
            O += (size_t)B_ * 1296;              // next t plane
        }
    }
}

// ---------------------------------------------------------------------------
extern "C" void kernel_launch(void* const* d_in, const int* in_sizes, int n_in,
                              void* d_out, int out_size) {
    const float* X   = (const float*)d_in[0];
    const float* h0  = (const float*)d_in[1];
    const float* s0  = (const float*)d_in[2];
    const float* Wl  = (const float*)d_in[3];
    const float* Ul  = (const float*)d_in[4];
    const float* bl  = (const float*)d_in[5];
    const float* Wew = (const float*)d_in[6];
    const float* Web = (const float*)d_in[7];
    const float* Uew = (const float*)d_in[8];
    const float* Ueb = (const float*)d_in[9];
    const float* vew = (const float*)d_in[10];
    // d_in[11] = ve_b: constant pre-softmax shift -> softmax-invariant, unused.
    float* out = (float*)d_out;

    cudaFuncSetAttribute(k_all, cudaFuncAttributeMaxDynamicSharedMemorySize, TOT_SMEM);
    k_all<<<B_, 512, TOT_SMEM>>>(X, h0, s0, Wl, Ul, bl,
                                 Wew, Web, Uew, Ueb, vew, out);
    (void)in_sizes; (void)n_in; (void)out_size;
}

// round 16
// speedup vs baseline: 1.1356x; 1.1356x over previous
#include <cuda_runtime.h>

#define B_  128
#define T_  64
#define N_  81
#define M_  128
#define G4_ 512

typedef unsigned long long ull;

__device__ __forceinline__ float frcp(float x) {
    float r; asm("rcp.approx.ftz.f32 %0, %1;" : "=f"(r) : "f"(x)); return r;
}
__device__ __forceinline__ float sigm(float x) {
    return frcp(1.0f + __expf(-x));
}
__device__ __forceinline__ float tanhe(float x) {           // exp-based, accurate
    return 2.0f * frcp(1.0f + __expf(-2.0f * x)) - 1.0f;
}
__device__ __forceinline__ float tanhap(float x) {          // HW tanh, 1 MUFU
    float r; asm("tanh.approx.f32 %0, %1;" : "=f"(r) : "f"(x)); return r;
}
__device__ __forceinline__ ull pk2(float a, float b) {
    ull r; asm("mov.b64 %0, {%1, %2};" : "=l"(r) : "f"(a), "f"(b)); return r;
}
__device__ __forceinline__ ull fma2(ull a, ull b, ull c) {
    ull d;
    asm("fma.rn.f32x2 %0, %1, %2, %3;" : "=l"(d) : "l"(a), "l"(b), "l"(c));
    return d;
}
__device__ __forceinline__ void unpk2(ull v, float& lo, float& hi) {
    asm("mov.b64 {%0, %1}, %2;" : "=f"(lo), "=f"(hi) : "l"(v));
}

// ---------------------------------------------------------------------------
// Shared-memory layout (floats). One block per b, 512 threads.
//  A-region: hc[64][257] = 16448; after phase-A done it is reused for
//            Us[96][65] = 6240.
//  B-region: Xst[81][66] = 5346 (gates, [k][t] transposed);
//            later Xs[5184] row-major (phases U / out).
//  C-region: Ws[81*256] = 20736 (gates, [k][c64][gate]);
//            later Wes chunk 4096 | As 64x65=4160 | Ues 4096 / LUT+AL.
// ---------------------------------------------------------------------------
#define HC_OFF   0
#define HC_PITCH 257
#define US_OFF   0                               // reuse of hc region
#define XB_OFF   16448                           // byte 65792, 16B aligned
#define XST_PITCH 66
#define C_OFF    21796                           // byte 87184, 16B aligned
#define WS_OFF   C_OFF                           // gates weights
#define WES_OFF  C_OFF                           // phase-A We_w chunk (4096)
#define AS_OFF   (C_OFF + 4096)                  // A 64x65, lives to end
#define UES_OFF  (C_OFF + 8256)                  // phase-U Ue_w (4096)
#define LUT_OFF  (C_OFF + 8256)                  // phase3 LUT (Ues dead); 16B ok
#define AL_OFF   (C_OFF + 8256 + 16 * 81 * 4)    // 16 warps * 81
#define Z_OFF    (C_OFF + 20736)                 // 42532: z[512]
#define VS_OFF   (Z_OFF + 512)                   // 43044
#define UB_OFF   (VS_OFF + 64)                   // 43108
#define HS_OFF   (UB_OFF + 64)                   // 43172: h0[128]
#define TOT_SMEM ((HS_OFF + 128) * 4)            // 173200 B

__global__ void __launch_bounds__(512, 1)
k_all(const float* __restrict__ X,   const float* __restrict__ h0,
      const float* __restrict__ s0,  const float* __restrict__ Wl,
      const float* __restrict__ Ul,  const float* __restrict__ bl,
      const float* __restrict__ Wew, const float* __restrict__ Web,
      const float* __restrict__ Uew, const float* __restrict__ Ueb,
      const float* __restrict__ vew, float* __restrict__ out) {
    extern __shared__ float sm[];
    float* hcsm = sm + HC_OFF;
    float* Xst  = sm + XB_OFF;
    float* Ws   = sm + WS_OFF;
    float* zsm  = sm + Z_OFF;
    float* vs   = sm + VS_OFF;
    float* ub   = sm + UB_OFF;
    float* hs   = sm + HS_OFF;
    int b = blockIdx.x, tid = threadIdx.x;
    int wid = tid >> 5, lane = tid & 31;

    // ---- prologue: Xst (transposed X), h0, vs, ub ----
    for (int idx = tid; idx < T_ * N_; idx += 512) {
        int t = idx / N_, k = idx - t * N_;
        Xst[k * XST_PITCH + t] = X[b * T_ * N_ + idx];
    }
    if (tid < M_) hs[tid] = h0[b * M_ + tid];
    else if (tid < M_ + 64)       vs[tid - M_]       = vew[tid - M_];
    else if (tid < M_ + 128)      ub[tid - M_ - 64]  = Ueb[tid - M_ - 64];
    __syncthreads();

    // ---- z = h0 @ U_lstm + b_lstm (one g per thread, deep-MLP unroll) ----
    {
        const float* Up = Ul + tid;
        float a0 = bl[tid], a1 = 0.f, a2 = 0.f, a3 = 0.f;
#pragma unroll
        for (int k = 0; k < M_; k += 16) {
            float u0  = Up[(k + 0)  * G4_], u1  = Up[(k + 1)  * G4_];
            float u2  = Up[(k + 2)  * G4_], u3  = Up[(k + 3)  * G4_];
            float u4  = Up[(k + 4)  * G4_], u5  = Up[(k + 5)  * G4_];
            float u6  = Up[(k + 6)  * G4_], u7  = Up[(k + 7)  * G4_];
            float u8  = Up[(k + 8)  * G4_], u9  = Up[(k + 9)  * G4_];
            float u10 = Up[(k + 10) * G4_], u11 = Up[(k + 11) * G4_];
            float u12 = Up[(k + 12) * G4_], u13 = Up[(k + 13) * G4_];
            float u14 = Up[(k + 14) * G4_], u15 = Up[(k + 15) * G4_];
            a0 += hs[k + 0]  * u0;  a1 += hs[k + 1]  * u1;
            a2 += hs[k + 2]  * u2;  a3 += hs[k + 3]  * u3;
            a0 += hs[k + 4]  * u4;  a1 += hs[k + 5]  * u5;
            a2 += hs[k + 6]  * u6;  a3 += hs[k + 7]  * u7;
            a0 += hs[k + 8]  * u8;  a1 += hs[k + 9]  * u9;
            a2 += hs[k + 10] * u10; a3 += hs[k + 11] * u11;
            a0 += hs[k + 12] * u12; a1 += hs[k + 13] * u13;
            a2 += hs[k + 14] * u14; a3 += hs[k + 15] * u15;
        }
        zsm[tid] = (a0 + a1) + (a2 + a3);
    }

    // ---- gates: X@W_lstm + z ; LSTM cell ; hc -> smem ----
    // warp = (t-group of 4: wid&7) x (m 32-band: wid>>3); loops: stage (m-half)
    // outer, th (t-half) inner — Ws loaded once per stage, used for both halves.
    {
        int tg = wid & 7, ml = wid >> 3;
        float sv_m[1];
        for (int stage = 0; stage < 2; stage++) {
            __syncthreads();
            for (int idx = tid; idx < 81 * 256; idx += 512) {
                int k = idx >> 8, j = idx & 255;
                int g = j >> 6, c = j & 63;
                Ws[k * 256 + c * 4 + g] = Wl[k * G4_ + g * M_ + stage * 64 + c];
            }
            __syncthreads();
            int m = stage * 64 + ml * 32 + lane;
            float zi = zsm[0 * M_ + m];
            float zf = zsm[1 * M_ + m];
            float zg = zsm[2 * M_ + m];
            float zo = zsm[3 * M_ + m];
            sv_m[0] = s0[b * M_ + m];

            for (int th = 0; th < 2; th++) {
                int trow = th * 32 + tg * 4;
                ull acc[4][2];
#pragma unroll
                for (int g = 0; g < 4; g++)
#pragma unroll
                    for (int p = 0; p < 2; p++) acc[g][p] = 0ull;

#pragma unroll 3
                for (int k = 0; k < 81; k++) {
                    const float* xr = &Xst[k * XST_PITCH + trow];
                    ull x0 = *(const ull*)(xr + 0);
                    ull x1 = *(const ull*)(xr + 2);
                    float4 w4 = *(const float4*)&Ws[k * 256 + (ml * 32 + lane) * 4];
                    ull di = pk2(w4.x, w4.x);
                    ull df = pk2(w4.y, w4.y);
                    ull dg = pk2(w4.z, w4.z);
                    ull do_ = pk2(w4.w, w4.w);
                    acc[0][0] = fma2(x0, di, acc[0][0]);
                    acc[0][1] = fma2(x1, di, acc[0][1]);
                    acc[1][0] = fma2(x0, df, acc[1][0]);
                    acc[1][1] = fma2(x1, df, acc[1][1]);
                    acc[2][0] = fma2(x0, dg, acc[2][0]);
                    acc[2][1] = fma2(x1, dg, acc[2][1]);
                    acc[3][0] = fma2(x0, do_, acc[3][0]);
                    acc[3][1] = fma2(x1, do_, acc[3][1]);
                }
#pragma unroll
                for (int p = 0; p < 2; p++) {
                    float vi[2], vf[2], vg[2], vo[2];
                    unpk2(acc[0][p], vi[0], vi[1]);
                    unpk2(acc[1][p], vf[0], vf[1]);
                    unpk2(acc[2][p], vg[0], vg[1]);
                    unpk2(acc[3][p], vo[0], vo[1]);
#pragma unroll
                    for (int hh_ = 0; hh_ < 2; hh_++) {
                        int t = trow + 2 * p + hh_;
                        float iv = sigm(vi[hh_] + zi);
                        float fv = sigm(vf[hh_] + zf);
                        float gv = tanhe(vg[hh_] + zg);
                        float ov = sigm(vo[hh_] + zo);
                        float cc = fv * sv_m[0] + iv * gv;
                        float hv = ov * tanhe(cc);
                        hcsm[t * HC_PITCH + m]       = hv;
                        hcsm[t * HC_PITCH + M_ + m]  = cc;
                    }
                }
            }
        }
    }

    // ---- phase A: A[t][j] = hc[t,:] @ We_w[:,j] + We_b[j], direct from hcsm ----
    float* As = sm + AS_OFF;
    {
        float* Wes = sm + WES_OFF;
        int r0 = (tid >> 4) * 2;
        int c0 = (tid & 15) * 4;
        float acc[2][4];
#pragma unroll
        for (int i = 0; i < 2; i++)
#pragma unroll
            for (int j = 0; j < 4; j++) acc[i][j] = Web[c0 + j];

        for (int kc = 0; kc < 4; kc++) {
            __syncthreads();                    // Ws (stage1) / prev Wes dead
            for (int idx = tid; idx < 4096; idx += 512)
                Wes[idx] = Wew[kc * 4096 + idx];
            __syncthreads();
#pragma unroll 4
            for (int k = 0; k < 64; k++) {
                float a0 = hcsm[r0 * HC_PITCH + kc * 64 + k];
                float a1 = hcsm[(r0 + 1) * HC_PITCH + kc * 64 + k];
                float4 w = *(const float4*)&Wes[k * 64 + c0];
                acc[0][0] += a0 * w.x; acc[0][1] += a0 * w.y;
                acc[0][2] += a0 * w.z; acc[0][3] += a0 * w.w;
                acc[1][0] += a1 * w.x; acc[1][1] += a1 * w.y;
                acc[1][2] += a1 * w.z; acc[1][3] += a1 * w.w;
            }
        }
        __syncthreads();                        // all hcsm reads done before As/Us writes
#pragma unroll
        for (int i = 0; i < 2; i++)
#pragma unroll
            for (int j = 0; j < 4; j++)
                As[(r0 + i) * 65 + c0 + j] = acc[i][j];
    }

    // ---- phase U: U[i][k] = sum_t X[b,t,i]*Ue_w[t,k] + Ue_b[k] ----
    // Xs (row-major) overwrites Xst; Us overwrites hcsm (dead after phase A).
    float* Us = sm + US_OFF;
    float* Xs = sm + XB_OFF;
    {
        float* Ues = sm + UES_OFF;
        for (int idx = tid; idx < 5184; idx += 512) Xs[idx] = X[b * 5184 + idx];
        for (int idx = tid; idx < 4096; idx += 512) Ues[idx] = Uew[idx];
        __syncthreads();

        if (tid < 336) {
            int ig = tid >> 4, kq = tid & 15, i0 = ig * 4;
            int ni = (i0 + 4 <= N_) ? 4 : (N_ - i0);
            float4 bias = *(const float4*)&ub[kq * 4];
            float4 a0 = bias, a1 = bias, a2 = bias, a3 = bias;
#pragma unroll 4
            for (int t = 0; t < T_; t++) {
                float4 u = *(const float4*)&Ues[t * 64 + kq * 4];
                const float* xr = &Xs[t * N_ + i0];
                float x0 = xr[0], x1 = xr[1], x2 = xr[2], x3 = xr[3];
                a0.x += x0 * u.x; a0.y += x0 * u.y; a0.z += x0 * u.z; a0.w += x0 * u.w;
                a1.x += x1 * u.x; a1.y += x1 * u.y; a1.z += x1 * u.z; a1.w += x1 * u.w;
                a2.x += x2 * u.x; a2.y += x2 * u.y; a2.z += x2 * u.z; a2.w += x2 * u.w;
                a3.x += x3 * u.x; a3.y += x3 * u.y; a3.z += x3 * u.z; a3.w += x3 * u.w;
            }
            float4 av[4] = {a0, a1, a2, a3};
            for (int j = 0; j < ni; j++) {
                float* up = &Us[(i0 + j) * 65 + kq * 4];
                up[0] = av[j].x; up[1] = av[j].y; up[2] = av[j].z; up[3] = av[j].w;
            }
        }
        // zero-pad rows 81..95 so lane+64 reads in phase 3 are in-region
        for (int idx = tid; idx < (96 - N_) * 65; idx += 512)
            Us[N_ * 65 + idx] = 0.0f;
    }

    // ---- phase 3: scores + softmax + fused output streaming ----
    __syncthreads();
    {
        bool v2 = (lane + 64 < N_);
        float*  alw = sm + AL_OFF + wid * 81;
        float4* lut = (float4*)(sm + LUT_OFF) + wid * 81;
        const float4* X4s = (const float4*)Xs;

        for (int t = wid; t < T_; t += 16) {
            float a0 = 0.f, a1 = 0.f, a2 = 0.f;
            const float* Ap = &As[t * 65];
            const float* U0 = &Us[lane * 65];
            const float* U1 = &Us[(lane + 32) * 65];
            const float* U2 = &Us[(lane + 64) * 65];
#pragma unroll 4
            for (int k = 0; k < 64; k++) {
                float av = Ap[k], vv = vs[k];
                a0 += vv * tanhap(av + U0[k]);
                a1 += vv * tanhap(av + U1[k]);
                a2 += vv * tanhap(av + U2[k]);
            }
            if (!v2) a2 = -1e30f;
            float mx = fmaxf(fmaxf(a0, a1), a2);
#pragma unroll
            for (int off = 16; off; off >>= 1)
                mx = fmaxf(mx, __shfl_xor_sync(0xffffffffu, mx, off));
            float e0 = __expf(a0 - mx);
            float e1 = __expf(a1 - mx);
            float e2 = __expf(a2 - mx);
            float sum = e0 + e1 + e2;
#pragma unroll
            for (int off = 16; off; off >>= 1)
                sum += __shfl_xor_sync(0xffffffffu, sum, off);
            float inv = frcp(sum);
            alw[lane]      = e0 * inv;
            alw[lane + 32] = e1 * inv;
            if (v2) alw[lane + 64] = e2 * inv;
            __syncwarp();

            // expanded float4 alpha LUT (period-81 mapping, gcd(4,81)=1)
#pragma unroll
            for (int rr = 0; rr < 3; rr++) {
                int r = lane + rr * 32;
                if (r < N_) {
                    int i0 = (4 * r) % N_;
                    int i1 = i0 + 1; if (i1 >= N_) i1 -= N_;
                    int i2 = i1 + 1; if (i2 >= N_) i2 -= N_;
                    int i3 = i2 + 1; if (i3 >= N_) i3 -= N_;
                    lut[r] = make_float4(alw[i0], alw[i1], alw[i2], alw[i3]);
                }
            }
            __syncwarp();

            float4* O = (float4*)out + (size_t)(t * B_ + b) * 1296;
            int r = lane % N_;
#pragma unroll 4
            for (int j = lane; j < 1296; j += 32) {
                float4 x = X4s[j];
                float4 a = lut[r];
                float4 o = make_float4(x.x * a.x, x.y * a.y, x.z * a.z, x.w * a.w);
                __stcs(&O[j], o);
                r += 32; if (r >= N_) r -= N_;
            }
            __syncwarp();
        }
    }
}

// ---------------------------------------------------------------------------
extern "C" void kernel_launch(void* const* d_in, const int* in_sizes, int n_in,
                              void* d_out, int out_size) {
    const float* X   = (const float*)d_in[0];
    const float* h0  = (const float*)d_in[1];
    const float* s0  = (const float*)d_in[2];
    const float* Wl  = (const float*)d_in[3];
    const float* Ul  = (const float*)d_in[4];
    const float* bl  = (const float*)d_in[5];
    const float* Wew = (const float*)d_in[6];
    const float* Web = (const float*)d_in[7];
    const float* Uew = (const float*)d_in[8];
    const float* Ueb = (const float*)d_in[9];
    const float* vew = (const float*)d_in[10];
    // d_in[11] = ve_b: constant pre-softmax shift -> softmax-invariant, unused.
    float* out = (float*)d_out;

    cudaFuncSetAttribute(k_all, cudaFuncAttributeMaxDynamicSharedMemorySize, TOT_SMEM);
    k_all<<<B_, 512, TOT_SMEM>>>(X, h0, s0, Wl, Ul, bl,
                                 Wew, Web, Uew, Ueb, vew, out);
    (void)in_sizes; (void)n_in; (void)out_size;
}

// round 17
// speedup vs baseline: 1.1653x; 1.0262x over previous
#include <cuda_runtime.h>

#define B_  128
#define T_  64
#define N_  81
#define M_  128
#define G4_ 512

typedef unsigned long long ull;

__device__ __forceinline__ float frcp(float x) {
    float r; asm("rcp.approx.ftz.f32 %0, %1;" : "=f"(r) : "f"(x)); return r;
}
__device__ __forceinline__ float sigm(float x) {
    return frcp(1.0f + __expf(-x));
}
__device__ __forceinline__ float tanhe(float x) {           // exp-based, accurate
    return 2.0f * frcp(1.0f + __expf(-2.0f * x)) - 1.0f;
}
__device__ __forceinline__ float tanhap(float x) {          // HW tanh, 1 MUFU
    float r; asm("tanh.approx.f32 %0, %1;" : "=f"(r) : "f"(x)); return r;
}
__device__ __forceinline__ ull pk2(float a, float b) {
    ull r; asm("mov.b64 %0, {%1, %2};" : "=l"(r) : "f"(a), "f"(b)); return r;
}
__device__ __forceinline__ ull fma2(ull a, ull b, ull c) {
    ull d;
    asm("fma.rn.f32x2 %0, %1, %2, %3;" : "=l"(d) : "l"(a), "l"(b), "l"(c));
    return d;
}
__device__ __forceinline__ void unpk2(ull v, float& lo, float& hi) {
    asm("mov.b64 {%0, %1}, %2;" : "=f"(lo), "=f"(hi) : "l"(v));
}

// ---------------------------------------------------------------------------
// Shared-memory layout (floats). One block per b, 512 threads.
//  A-region: hc[64][257] = 16448; after phase-A done it is reused for
//            Us[96][65] = 6240.
//  B-region: Xst[81][66] = 5346 (gates, [k][t] transposed);
//            later Xs[5184] row-major (phases U / out).
//  C-region: Ws[81*256] = 20736 (gates, [k][c64][gate]);
//            later Wes chunk 4096 | As 64x65=4160 | Ues 4096 / LUT+AL.
// ---------------------------------------------------------------------------
#define HC_OFF   0
#define HC_PITCH 257
#define US_OFF   0                               // reuse of hc region
#define XB_OFF   16448                           // byte 65792, 16B aligned
#define XST_PITCH 66
#define C_OFF    21796                           // byte 87184, 16B aligned
#define WS_OFF   C_OFF                           // gates weights
#define WES_OFF  C_OFF                           // phase-A We_w chunk (4096)
#define AS_OFF   (C_OFF + 4096)                  // A 64x65, lives to end
#define UES_OFF  (C_OFF + 8256)                  // phase-U Ue_w (4096)
#define LUT_OFF  (C_OFF + 8256)                  // phase3 LUT (Ues dead); 16B ok
#define AL_OFF   (C_OFF + 8256 + 16 * 81 * 4)    // 16 warps * 81
#define Z_OFF    (C_OFF + 20736)                 // 42532: z[512]
#define VS_OFF   (Z_OFF + 512)                   // 43044
#define UB_OFF   (VS_OFF + 64)                   // 43108
#define HS_OFF   (UB_OFF + 64)                   // 43172: h0[128]
#define TOT_SMEM ((HS_OFF + 128) * 4)            // 173200 B

__global__ void __launch_bounds__(512, 1)
k_all(const float* __restrict__ X,   const float* __restrict__ h0,
      const float* __restrict__ s0,  const float* __restrict__ Wl,
      const float* __restrict__ Ul,  const float* __restrict__ bl,
      const float* __restrict__ Wew, const float* __restrict__ Web,
      const float* __restrict__ Uew, const float* __restrict__ Ueb,
      const float* __restrict__ vew, float* __restrict__ out) {
    extern __shared__ float sm[];
    float* hcsm = sm + HC_OFF;
    float* Xst  = sm + XB_OFF;
    float* Ws   = sm + WS_OFF;
    float* zsm  = sm + Z_OFF;
    float* vs   = sm + VS_OFF;
    float* ub   = sm + UB_OFF;
    float* hs   = sm + HS_OFF;
    int b = blockIdx.x, tid = threadIdx.x;
    int wid = tid >> 5, lane = tid & 31;

    // ---- prologue: Xst (transposed X), h0, vs, ub ----
    for (int idx = tid; idx < T_ * N_; idx += 512) {
        int t = idx / N_, k = idx - t * N_;
        Xst[k * XST_PITCH + t] = X[b * T_ * N_ + idx];
    }
    if (tid < M_) hs[tid] = h0[b * M_ + tid];
    else if (tid < M_ + 64)       vs[tid - M_]       = vew[tid - M_];
    else if (tid < M_ + 128)      ub[tid - M_ - 64]  = Ueb[tid - M_ - 64];
    __syncthreads();

    // ---- z = h0 @ U_lstm + b_lstm (one g per thread, deep-MLP unroll) ----
    {
        const float* Up = Ul + tid;
        float a0 = bl[tid], a1 = 0.f, a2 = 0.f, a3 = 0.f;
#pragma unroll
        for (int k = 0; k < M_; k += 16) {
            float u0  = Up[(k + 0)  * G4_], u1  = Up[(k + 1)  * G4_];
            float u2  = Up[(k + 2)  * G4_], u3  = Up[(k + 3)  * G4_];
            float u4  = Up[(k + 4)  * G4_], u5  = Up[(k + 5)  * G4_];
            float u6  = Up[(k + 6)  * G4_], u7  = Up[(k + 7)  * G4_];
            float u8  = Up[(k + 8)  * G4_], u9  = Up[(k + 9)  * G4_];
            float u10 = Up[(k + 10) * G4_], u11 = Up[(k + 11) * G4_];
            float u12 = Up[(k + 12) * G4_], u13 = Up[(k + 13) * G4_];
            float u14 = Up[(k + 14) * G4_], u15 = Up[(k + 15) * G4_];
            a0 += hs[k + 0]  * u0;  a1 += hs[k + 1]  * u1;
            a2 += hs[k + 2]  * u2;  a3 += hs[k + 3]  * u3;
            a0 += hs[k + 4]  * u4;  a1 += hs[k + 5]  * u5;
            a2 += hs[k + 6]  * u6;  a3 += hs[k + 7]  * u7;
            a0 += hs[k + 8]  * u8;  a1 += hs[k + 9]  * u9;
            a2 += hs[k + 10] * u10; a3 += hs[k + 11] * u11;
            a0 += hs[k + 12] * u12; a1 += hs[k + 13] * u13;
            a2 += hs[k + 14] * u14; a3 += hs[k + 15] * u15;
        }
        zsm[tid] = (a0 + a1) + (a2 + a3);
    }

    // ---- gates: X@W_lstm + z ; LSTM cell ; hc -> smem ----
    // warp = (t-group of 4: wid&7) x (m 32-band: wid>>3); loops: stage (m-half)
    // outer, th (t-half) inner — Ws loaded once per stage, used for both halves.
    {
        int tg = wid & 7, ml = wid >> 3;
        float sv_m[1];
        for (int stage = 0; stage < 2; stage++) {
            __syncthreads();
            for (int idx = tid; idx < 81 * 256; idx += 512) {
                int k = idx >> 8, j = idx & 255;
                int g = j >> 6, c = j & 63;
                Ws[k * 256 + c * 4 + g] = Wl[k * G4_ + g * M_ + stage * 64 + c];
            }
            __syncthreads();
            int m = stage * 64 + ml * 32 + lane;
            float zi = zsm[0 * M_ + m];
            float zf = zsm[1 * M_ + m];
            float zg = zsm[2 * M_ + m];
            float zo = zsm[3 * M_ + m];
            sv_m[0] = s0[b * M_ + m];

            for (int th = 0; th < 2; th++) {
                int trow = th * 32 + tg * 4;
                ull acc[4][2];
#pragma unroll
                for (int g = 0; g < 4; g++)
#pragma unroll
                    for (int p = 0; p < 2; p++) acc[g][p] = 0ull;

#pragma unroll 3
                for (int k = 0; k < 81; k++) {
                    const float* xr = &Xst[k * XST_PITCH + trow];
                    ull x0 = *(const ull*)(xr + 0);
                    ull x1 = *(const ull*)(xr + 2);
                    float4 w4 = *(const float4*)&Ws[k * 256 + (ml * 32 + lane) * 4];
                    ull di = pk2(w4.x, w4.x);
                    ull df = pk2(w4.y, w4.y);
                    ull dg = pk2(w4.z, w4.z);
                    ull do_ = pk2(w4.w, w4.w);
                    acc[0][0] = fma2(x0, di, acc[0][0]);
                    acc[0][1] = fma2(x1, di, acc[0][1]);
                    acc[1][0] = fma2(x0, df, acc[1][0]);
                    acc[1][1] = fma2(x1, df, acc[1][1]);
                    acc[2][0] = fma2(x0, dg, acc[2][0]);
                    acc[2][1] = fma2(x1, dg, acc[2][1]);
                    acc[3][0] = fma2(x0, do_, acc[3][0]);
                    acc[3][1] = fma2(x1, do_, acc[3][1]);
                }
#pragma unroll
                for (int p = 0; p < 2; p++) {
                    float vi[2], vf[2], vg[2], vo[2];
                    unpk2(acc[0][p], vi[0], vi[1]);
                    unpk2(acc[1][p], vf[0], vf[1]);
                    unpk2(acc[2][p], vg[0], vg[1]);
                    unpk2(acc[3][p], vo[0], vo[1]);
#pragma unroll
                    for (int hh_ = 0; hh_ < 2; hh_++) {
                        int t = trow + 2 * p + hh_;
                        float iv = sigm(vi[hh_] + zi);
                        float fv = sigm(vf[hh_] + zf);
                        float gv = tanhe(vg[hh_] + zg);
                        float ov = sigm(vo[hh_] + zo);
                        float cc = fv * sv_m[0] + iv * gv;
                        float hv = ov * tanhe(cc);
                        hcsm[t * HC_PITCH + m]       = hv;
                        hcsm[t * HC_PITCH + M_ + m]  = cc;
                    }
                }
            }
        }
    }

    // ---- phase A: A[t][j] = hc[t,:] @ We_w[:,j] + We_b[j], direct from hcsm ----
    float* As = sm + AS_OFF;
    {
        float* Wes = sm + WES_OFF;
        int r0 = (tid >> 4) * 2;
        int c0 = (tid & 15) * 4;
        float acc[2][4];
#pragma unroll
        for (int i = 0; i < 2; i++)
#pragma unroll
            for (int j = 0; j < 4; j++) acc[i][j] = Web[c0 + j];

        for (int kc = 0; kc < 4; kc++) {
            __syncthreads();                    // Ws (stage1) / prev Wes dead
            for (int idx = tid; idx < 4096; idx += 512)
                Wes[idx] = Wew[kc * 4096 + idx];
            __syncthreads();
#pragma unroll 4
            for (int k = 0; k < 64; k++) {
                float a0 = hcsm[r0 * HC_PITCH + kc * 64 + k];
                float a1 = hcsm[(r0 + 1) * HC_PITCH + kc * 64 + k];
                float4 w = *(const float4*)&Wes[k * 64 + c0];
                acc[0][0] += a0 * w.x; acc[0][1] += a0 * w.y;
                acc[0][2] += a0 * w.z; acc[0][3] += a0 * w.w;
                acc[1][0] += a1 * w.x; acc[1][1] += a1 * w.y;
                acc[1][2] += a1 * w.z; acc[1][3] += a1 * w.w;
            }
        }
        __syncthreads();                        // all hcsm reads done before As/Us writes
#pragma unroll
        for (int i = 0; i < 2; i++)
#pragma unroll
            for (int j = 0; j < 4; j++)
                As[(r0 + i) * 65 + c0 + j] = acc[i][j];
    }

    // ---- phase U: U[i][k] = sum_t X[b,t,i]*Ue_w[t,k] + Ue_b[k] ----
    // Xs (row-major) overwrites Xst; Us overwrites hcsm (dead after phase A).
    float* Us = sm + US_OFF;
    float* Xs = sm + XB_OFF;
    {
        float* Ues = sm + UES_OFF;
        for (int idx = tid; idx < 5184; idx += 512) Xs[idx] = X[b * 5184 + idx];
        for (int idx = tid; idx < 4096; idx += 512) Ues[idx] = Uew[idx];
        __syncthreads();

        if (tid < 336) {
            int ig = tid >> 4, kq = tid & 15, i0 = ig * 4;
            int ni = (i0 + 4 <= N_) ? 4 : (N_ - i0);
            float4 bias = *(const float4*)&ub[kq * 4];
            float4 a0 = bias, a1 = bias, a2 = bias, a3 = bias;
#pragma unroll 4
            for (int t = 0; t < T_; t++) {
                float4 u = *(const float4*)&Ues[t * 64 + kq * 4];
                const float* xr = &Xs[t * N_ + i0];
                float x0 = xr[0], x1 = xr[1], x2 = xr[2], x3 = xr[3];
                a0.x += x0 * u.x; a0.y += x0 * u.y; a0.z += x0 * u.z; a0.w += x0 * u.w;
                a1.x += x1 * u.x; a1.y += x1 * u.y; a1.z += x1 * u.z; a1.w += x1 * u.w;
                a2.x += x2 * u.x; a2.y += x2 * u.y; a2.z += x2 * u.z; a2.w += x2 * u.w;
                a3.x += x3 * u.x; a3.y += x3 * u.y; a3.z += x3 * u.z; a3.w += x3 * u.w;
            }
            float4 av[4] = {a0, a1, a2, a3};
            for (int j = 0; j < ni; j++) {
                float* up = &Us[(i0 + j) * 65 + kq * 4];
                up[0] = av[j].x; up[1] = av[j].y; up[2] = av[j].z; up[3] = av[j].w;
            }
        }
        // zero-pad rows 81..95 so lane+64 reads in phase 3 are in-region
        for (int idx = tid; idx < (96 - N_) * 65; idx += 512)
            Us[N_ * 65 + idx] = 0.0f;
    }

    // ---- phase 3: scores + softmax + fused output streaming ----
    __syncthreads();
    {
        bool v2 = (lane + 64 < N_);
        float*  alw = sm + AL_OFF + wid * 81;
        float4* lut = (float4*)(sm + LUT_OFF) + wid * 81;
        const float4* X4s = (const float4*)Xs;

        for (int t = wid; t < T_; t += 16) {
            float a0 = 0.f, a1 = 0.f, a2 = 0.f;
            const float* Ap = &As[t * 65];
            const float* U0 = &Us[lane * 65];
            const float* U1 = &Us[(lane + 32) * 65];
            const float* U2 = &Us[(lane + 64) * 65];
#pragma unroll 4
            for (int k = 0; k < 64; k++) {
                float av = Ap[k], vv = vs[k];
                a0 += vv * tanhap(av + U0[k]);
                a1 += vv * tanhap(av + U1[k]);
                a2 += vv * tanhap(av + U2[k]);
            }
            if (!v2) a2 = -1e30f;
            float mx = fmaxf(fmaxf(a0, a1), a2);
#pragma unroll
            for (int off = 16; off; off >>= 1)
                mx = fmaxf(mx, __shfl_xor_sync(0xffffffffu, mx, off));
            float e0 = __expf(a0 - mx);
            float e1 = __expf(a1 - mx);
            float e2 = __expf(a2 - mx);
            float sum = e0 + e1 + e2;
#pragma unroll
            for (int off = 16; off; off >>= 1)
                sum += __shfl_xor_sync(0xffffffffu, sum, off);
            float inv = frcp(sum);
            alw[lane]      = e0 * inv;
            alw[lane + 32] = e1 * inv;
            if (v2) alw[lane + 64] = e2 * inv;
            __syncwarp();

            // expanded float4 alpha LUT (period-81 mapping, gcd(4,81)=1)
#pragma unroll
            for (int rr = 0; rr < 3; rr++) {
                int r = lane + rr * 32;
                if (r < N_) {
                    int i0 = (4 * r) % N_;
                    int i1 = i0 + 1; if (i1 >= N_) i1 -= N_;
                    int i2 = i1 + 1; if (i2 >= N_) i2 -= N_;
                    int i3 = i2 + 1; if (i3 >= N_) i3 -= N_;
                    lut[r] = make_float4(alw[i0], alw[i1], alw[i2], alw[i3]);
                }
            }
            __syncwarp();

            float4* O = (float4*)out + (size_t)(t * B_ + b) * 1296;
            int r = lane % N_;
#pragma unroll 4
            for (int j = lane; j < 1296; j += 32) {
                float4 x = X4s[j];
                float4 a = lut[r];
                float4 o = make_float4(x.x * a.x, x.y * a.y, x.z * a.z, x.w * a.w);
                __stcs(&O[j], o);
                r += 32; if (r >= N_) r -= N_;
            }
            __syncwarp();
        }
    }
}

// ---------------------------------------------------------------------------
extern "C" void kernel_launch(void* const* d_in, const int* in_sizes, int n_in,
                              void* d_out, int out_size) {
    const float* X   = (const float*)d_in[0];
    const float* h0  = (const float*)d_in[1];
    const float* s0  = (const float*)d_in[2];
    const float* Wl  = (const float*)d_in[3];
    const float* Ul  = (const float*)d_in[4];
    const float* bl  = (const float*)d_in[5];
    const float* Wew = (const float*)d_in[6];
    const float* Web = (const float*)d_in[7];
    const float* Uew = (const float*)d_in[8];
    const float* Ueb = (const float*)d_in[9];
    const float* vew = (const float*)d_in[10];
    // d_in[11] = ve_b: constant pre-softmax shift -> softmax-invariant, unused.
    float* out = (float*)d_out;

    cudaFuncSetAttribute(k_all, cudaFuncAttributeMaxDynamicSharedMemorySize, TOT_SMEM);
    k_all<<<B_, 512, TOT_SMEM>>>(X, h0, s0, Wl, Ul, bl,
                                 Wew, Web, Uew, Ueb, vew, out);
    (void)in_sizes; (void)n_in; (void)out_size;
}